// round 3
// baseline (speedup 1.0000x reference)
#include <cuda_runtime.h>
#include <math.h>

#define NG    320
#define NS1   (NG*NG)
#define NSHOT 2
#define NSRC  8
#define NREC  96
#define NT    160
#define PML_W 20
#define NBLK  200
#define TPB   256
#define NPAIR (NG/2)          // 160 pairs per row
#define IDHF  0.25f
#define DTF   4.0e-4f

// Global wave fields (neighbors read them). CPML memory variables live in
// registers of the owning thread.
__device__ float g_vy [NSHOT*NS1];
__device__ float g_vx [NSHOT*NS1];
__device__ float g_syy[NSHOT*NS1];
__device__ float g_sxy[NSHOT*NS1];
__device__ float g_sxx[NSHOT*NS1];
__device__ float g_recs[NT*NSHOT*NREC];

__device__ __align__(128) unsigned g_count = 0;
__device__ __align__(128) volatile unsigned g_phase = 0;

// Grid-wide barrier (cooperative-groups pattern). g_phase is monotonic across
// graph replays; targets are relative to the value read at kernel start.
__device__ __forceinline__ void gbar(unsigned target)
{
    __syncthreads();
    if (threadIdx.x == 0) {
        __threadfence();
        if (atomicAdd(&g_count, 1u) == NBLK - 1) {
            g_count = 0;
            __threadfence();
            g_phase = target;
        } else {
            while ((int)(g_phase - target) < 0) { }
        }
        __threadfence();
    }
    __syncthreads();
}

__device__ __forceinline__ float pml_b(int i)
{
    const double d0 = 3.0 * 1600.0 * log(1000.0) / (2.0 * PML_W * 4.0);
    double dd = 0.0;
    if (i < PML_W) {
        double a = (double)(PML_W - i) / PML_W;
        dd = d0 * a * a;
    } else if (i >= NG - PML_W) {
        double a = ((double)i - (NG - 1 - PML_W)) / PML_W;
        dd = d0 * a * a;
    }
    return (float)exp(-dd * 4.0e-4);
}

__device__ __forceinline__ float2 ld2(const float* __restrict__ p, int idx)
{
    return *reinterpret_cast<const float2*>(p + idx);
}
__device__ __forceinline__ void st2(float* __restrict__ p, int idx, float a, float b)
{
    *reinterpret_cast<float2*>(p + idx) = make_float2(a, b);
}

__global__ __launch_bounds__(TPB, 2) void sim_kernel(
    const float* __restrict__ lamb,
    const float* __restrict__ mu,
    const float* __restrict__ buoy,
    const float* __restrict__ amps,   // [NSHOT, NSRC, NT]
    const int*   __restrict__ sloc,   // [NSHOT, NSRC, 2]
    const int*   __restrict__ rloc,   // [NSHOT, NREC, 2]
    float* __restrict__ out)          // [NSHOT, NREC, NT-1]
{
    const int pair = blockIdx.x * TPB + threadIdx.x;   // 0..51199
    const int y  = pair / NPAIR;
    const int x0 = (pair - y * NPAIR) * 2;             // even column
    unsigned ph = g_phase;

    // wrapped rows (wraparound only matters at masked border cells)
    const int ym1 = (y == 0)      ? NG - 1     : y - 1;
    const int ym2 = (y <= 1)      ? y + NG - 2 : y - 2;
    const int yp1 = (y == NG - 1) ? 0          : y + 1;
    const int yp2 = (y >= NG - 2) ? y - (NG-2) : y + 2;

    const int row  = y   * NG;
    const int rym1 = ym1 * NG, rym2 = ym2 * NG;
    const int ryp1 = yp1 * NG, ryp2 = yp2 * NG;

    // wrapped even x columns for float2 taps
    const int xm2c = (x0 == 0)      ? NG - 2 : x0 - 2;   // cols x0-2, x0-1
    const int xp2c = (x0 == NG - 2) ? 0      : x0 + 2;   // cols x0+2, x0+3

    const int o = row + x0;   // own pair position (even)

    const float byv  = pml_b(y);
    const float bxv0 = pml_b(x0);
    const float bxv1 = pml_b(x0 + 1);

    const float2 bv2  = ld2(buoy, o);
    const float2 lam2 = ld2(lamb, o);
    const float2 mu2  = ld2(mu,   o);
    const float l2m0 = lam2.x + 2.0f * mu2.x;
    const float l2m1 = lam2.y + 2.0f * mu2.y;

    const bool ybord = (y < 2 || y >= NG - 2);
    const float mk0 = (ybord || x0     < 2 || x0     >= NG - 2) ? 0.0f : 1.0f;
    const float mk1 = (ybord || x0 + 1 < 2 || x0 + 1 >= NG - 2) ? 0.0f : 1.0f;

    // source membership: bit s -> cell0, bit s+8 -> cell1
    unsigned smask[2] = {0u, 0u};
#pragma unroll
    for (int b = 0; b < NSHOT; b++) {
#pragma unroll
        for (int s = 0; s < NSRC; s++) {
            int sy = sloc[(b*NSRC + s)*2];
            int sx = sloc[(b*NSRC + s)*2 + 1];
            if (sy == y && sx == x0)     smask[b] |= 1u << s;
            if (sy == y && sx == x0 + 1) smask[b] |= 1u << (s + 8);
        }
    }

    // register-resident state [shot][cell]
    float vy[2][2]  = {{0,0},{0,0}}, vx[2][2]  = {{0,0},{0,0}};
    float syy[2][2] = {{0,0},{0,0}}, sxy[2][2] = {{0,0},{0,0}}, sxx[2][2] = {{0,0},{0,0}};
    float m_vyy[2][2]  = {{0,0},{0,0}}, m_vyx[2][2]  = {{0,0},{0,0}};
    float m_vxy[2][2]  = {{0,0},{0,0}}, m_vxx[2][2]  = {{0,0},{0,0}};
    float m_syyy[2][2] = {{0,0},{0,0}}, m_sxyy[2][2] = {{0,0},{0,0}};
    float m_sxyx[2][2] = {{0,0},{0,0}}, m_sxxx[2][2] = {{0,0},{0,0}};

    // zero global fields
#pragma unroll
    for (int b = 0; b < NSHOT; b++) {
        int i = b * NS1 + o;
        st2(g_vy,  i, 0.f, 0.f);
        st2(g_vx,  i, 0.f, 0.f);
        st2(g_syy, i, 0.f, 0.f);
        st2(g_sxy, i, 0.f, 0.f);
        st2(g_sxx, i, 0.f, 0.f);
    }
    gbar(++ph);

    const float C1 = 1.125f;
    const float C2 = -1.0f / 24.0f;

    for (int t = 0; t < NT; t++) {
        // ======================= velocity phase =======================
#pragma unroll
        for (int b = 0; b < NSHOT; b++) {
            const int base = b * NS1;
            float d0, d1, m;

            // Dy^-(syy): taps ym1, ym2, yp1 (own in reg)
            float2 a_ym1 = ld2(g_syy, base + rym1 + x0);
            float2 a_ym2 = ld2(g_syy, base + rym2 + x0);
            float2 a_yp1 = ld2(g_syy, base + ryp1 + x0);
            d0 = (C1*(syy[b][0] - a_ym1.x) + C2*(a_yp1.x - a_ym2.x)) * IDHF;
            d1 = (C1*(syy[b][1] - a_ym1.y) + C2*(a_yp1.y - a_ym2.y)) * IDHF;
            m = m_syyy[b][0]; m = byv*m + (byv-1.0f)*d0; m_syyy[b][0] = m;
            float ay0 = d0 + m;
            m = m_syyy[b][1]; m = byv*m + (byv-1.0f)*d1; m_syyy[b][1] = m;
            float ay1 = d1 + m;

            // Dx^+(sxy): taps xm1, xp1, xp2
            float2 u_xm = ld2(g_sxy, base + row + xm2c);
            float2 u_xp = ld2(g_sxy, base + row + xp2c);
            d0 = (C1*(sxy[b][1] - sxy[b][0]) + C2*(u_xp.x - u_xm.y)) * IDHF;
            d1 = (C1*(u_xp.x   - sxy[b][1]) + C2*(u_xp.y - sxy[b][0])) * IDHF;
            m = m_sxyx[b][0]; m = bxv0*m + (bxv0-1.0f)*d0; m_sxyx[b][0] = m;
            ay0 += d0 + m;
            m = m_sxyx[b][1]; m = bxv1*m + (bxv1-1.0f)*d1; m_sxyx[b][1] = m;
            ay1 += d1 + m;

            vy[b][0] += DTF * bv2.x * ay0;
            vy[b][1] += DTF * bv2.y * ay1;

            // Dx^-(sxx): taps xm1, xm2, xp1
            float2 w_xm = ld2(g_sxx, base + row + xm2c);
            float2 w_xp = ld2(g_sxx, base + row + xp2c);
            d0 = (C1*(sxx[b][0] - w_xm.y) + C2*(sxx[b][1] - w_xm.x)) * IDHF;
            d1 = (C1*(sxx[b][1] - sxx[b][0]) + C2*(w_xp.x - w_xm.y)) * IDHF;
            m = m_sxxx[b][0]; m = bxv0*m + (bxv0-1.0f)*d0; m_sxxx[b][0] = m;
            float ax0 = d0 + m;
            m = m_sxxx[b][1]; m = bxv1*m + (bxv1-1.0f)*d1; m_sxxx[b][1] = m;
            float ax1 = d1 + m;

            // Dy^+(sxy): taps yp1, yp2, ym1
            float2 s_yp1 = ld2(g_sxy, base + ryp1 + x0);
            float2 s_yp2 = ld2(g_sxy, base + ryp2 + x0);
            float2 s_ym1 = ld2(g_sxy, base + rym1 + x0);
            d0 = (C1*(s_yp1.x - sxy[b][0]) + C2*(s_yp2.x - s_ym1.x)) * IDHF;
            d1 = (C1*(s_yp1.y - sxy[b][1]) + C2*(s_yp2.y - s_ym1.y)) * IDHF;
            m = m_sxyy[b][0]; m = byv*m + (byv-1.0f)*d0; m_sxyy[b][0] = m;
            ax0 += d0 + m;
            m = m_sxyy[b][1]; m = byv*m + (byv-1.0f)*d1; m_sxyy[b][1] = m;
            ax1 += d1 + m;

            vx[b][0] += DTF * bv2.x * ax0;
            vx[b][1] += DTF * bv2.y * ax1;

            // source injection (src_buoy == buoyancy at the source cell)
            if (smask[b]) {
#pragma unroll
                for (int s = 0; s < NSRC; s++) {
                    if (smask[b] & (1u << s))
                        vy[b][0] += DTF * amps[(b*NSRC + s)*NT + t] * bv2.x;
                    if (smask[b] & (1u << (s + 8)))
                        vy[b][1] += DTF * amps[(b*NSRC + s)*NT + t] * bv2.y;
                }
            }
            vy[b][0] *= mk0; vy[b][1] *= mk1;
            vx[b][0] *= mk0; vx[b][1] *= mk1;
            st2(g_vy, base + o, vy[b][0], vy[b][1]);
            st2(g_vx, base + o, vx[b][0], vx[b][1]);
        }
        gbar(++ph);

        // receivers: vy is read-only during the stress phase -> race-free
        if (pair < NSHOT * NREC) {
            int rb = pair / NREC, r = pair - rb * NREC;
            int ry = rloc[(rb*NREC + r)*2];
            int rx = rloc[(rb*NREC + r)*2 + 1];
            g_recs[(t*NSHOT + rb)*NREC + r] = g_vy[rb*NS1 + ry*NG + rx];
        }

        // ======================= stress phase =======================
#pragma unroll
        for (int b = 0; b < NSHOT; b++) {
            const int base = b * NS1;
            float d0, d1, m;

            // Dy^+(vy): taps yp1, yp2, ym1
            float2 a_yp1 = ld2(g_vy, base + ryp1 + x0);
            float2 a_yp2 = ld2(g_vy, base + ryp2 + x0);
            float2 a_ym1 = ld2(g_vy, base + rym1 + x0);
            d0 = (C1*(a_yp1.x - vy[b][0]) + C2*(a_yp2.x - a_ym1.x)) * IDHF;
            d1 = (C1*(a_yp1.y - vy[b][1]) + C2*(a_yp2.y - a_ym1.y)) * IDHF;
            m = m_vyy[b][0]; m = byv*m + (byv-1.0f)*d0; m_vyy[b][0] = m;
            float e10 = d0 + m;
            m = m_vyy[b][1]; m = byv*m + (byv-1.0f)*d1; m_vyy[b][1] = m;
            float e11 = d1 + m;

            // Dx^-(vx): taps xm1, xm2, xp1
            float2 vx_xm = ld2(g_vx, base + row + xm2c);
            float2 vx_xp = ld2(g_vx, base + row + xp2c);
            d0 = (C1*(vx[b][0] - vx_xm.y) + C2*(vx[b][1] - vx_xm.x)) * IDHF;
            d1 = (C1*(vx[b][1] - vx[b][0]) + C2*(vx_xp.x - vx_xm.y)) * IDHF;
            m = m_vxx[b][0]; m = bxv0*m + (bxv0-1.0f)*d0; m_vxx[b][0] = m;
            float e20 = d0 + m;
            m = m_vxx[b][1]; m = bxv1*m + (bxv1-1.0f)*d1; m_vxx[b][1] = m;
            float e21 = d1 + m;

            syy[b][0] = (syy[b][0] + DTF*(l2m0*e10 + lam2.x*e20)) * mk0;
            syy[b][1] = (syy[b][1] + DTF*(l2m1*e11 + lam2.y*e21)) * mk1;
            sxx[b][0] = (sxx[b][0] + DTF*(l2m0*e20 + lam2.x*e10)) * mk0;
            sxx[b][1] = (sxx[b][1] + DTF*(l2m1*e21 + lam2.y*e11)) * mk1;

            // Dx^+(vy): taps xp1, xp2, xm1
            float2 vy_xm = ld2(g_vy, base + row + xm2c);
            float2 vy_xp = ld2(g_vy, base + row + xp2c);
            d0 = (C1*(vy[b][1] - vy[b][0]) + C2*(vy_xp.x - vy_xm.y)) * IDHF;
            d1 = (C1*(vy_xp.x - vy[b][1]) + C2*(vy_xp.y - vy[b][0])) * IDHF;
            m = m_vyx[b][0]; m = bxv0*m + (bxv0-1.0f)*d0; m_vyx[b][0] = m;
            float g0 = d0 + m;
            m = m_vyx[b][1]; m = bxv1*m + (bxv1-1.0f)*d1; m_vyx[b][1] = m;
            float g1 = d1 + m;

            // Dy^-(vx): taps ym1, ym2, yp1
            float2 x_ym1 = ld2(g_vx, base + rym1 + x0);
            float2 x_ym2 = ld2(g_vx, base + rym2 + x0);
            float2 x_yp1 = ld2(g_vx, base + ryp1 + x0);
            d0 = (C1*(vx[b][0] - x_ym1.x) + C2*(x_yp1.x - x_ym2.x)) * IDHF;
            d1 = (C1*(vx[b][1] - x_ym1.y) + C2*(x_yp1.y - x_ym2.y)) * IDHF;
            m = m_vxy[b][0]; m = byv*m + (byv-1.0f)*d0; m_vxy[b][0] = m;
            g0 += d0 + m;
            m = m_vxy[b][1]; m = byv*m + (byv-1.0f)*d1; m_vxy[b][1] = m;
            g1 += d1 + m;

            sxy[b][0] = (sxy[b][0] + DTF*mu2.x*g0) * mk0;
            sxy[b][1] = (sxy[b][1] + DTF*mu2.y*g1) * mk1;

            st2(g_syy, base + o, syy[b][0], syy[b][1]);
            st2(g_sxy, base + o, sxy[b][0], sxy[b][1]);
            st2(g_sxx, base + o, sxx[b][0], sxx[b][1]);
        }
        gbar(++ph);
    }

    // ---------------- finalize ----------------
    const int total = NSHOT * NREC * (NT - 1);
    if (pair < total) {
        int t = pair % (NT - 1);
        int r = (pair / (NT - 1)) % NREC;
        int b = pair / ((NT - 1) * NREC);
        out[pair] = 0.5f * (g_recs[((t + 1)*NSHOT + b)*NREC + r]
                          + g_recs[(t      *NSHOT + b)*NREC + r]);
    }
}

extern "C" void kernel_launch(void* const* d_in, const int* in_sizes, int n_in,
                              void* d_out, int out_size)
{
    const float* lamb = (const float*)d_in[0];
    const float* mu   = (const float*)d_in[1];
    const float* buoy = (const float*)d_in[2];
    const float* amps = (const float*)d_in[3];
    const int*   sloc = (const int*)d_in[4];
    const int*   rloc = (const int*)d_in[5];
    float* out = (float*)d_out;

    sim_kernel<<<NBLK, TPB>>>(lamb, mu, buoy, amps, sloc, rloc, out);
}

// round 4
// speedup vs baseline: 1.2645x; 1.2645x over previous
#include <cuda_runtime.h>
#include <math.h>

#define NG     320
#define NS1    (NG*NG)
#define NSHOT  2
#define NSRC   8
#define NREC   96
#define NT     160
#define PML_W  20
#define NBLK   128
#define TPB    400
#define TILE_R 20
#define TILE_C 40
#define TCB    8            // tile columns of blocks (320/40)
#define NPR    (TILE_C/2)   // 20 pairs per tile row
#define NRING  240
#define EXT_R  24
#define EXT_C  45           // 44 used + 1 pad
#define IDHF   0.25f
#define DTF    4.0e-4f

// Double-buffered global stress. Velocity lives only in registers/SMEM.
__device__ float g_syy[2][NSHOT*NS1];
__device__ float g_sxy[2][NSHOT*NS1];
__device__ float g_sxx[2][NSHOT*NS1];
__device__ float g_recs[NT*NSHOT*NREC];

__device__ __align__(128) unsigned g_count = 0;
__device__ __align__(128) volatile unsigned g_phase = 0;

__device__ __forceinline__ void gbar(unsigned target)
{
    __syncthreads();
    if (threadIdx.x == 0) {
        __threadfence();
        if (atomicAdd(&g_count, 1u) == NBLK - 1) {
            g_count = 0;
            __threadfence();
            g_phase = target;
        } else {
            while ((int)(g_phase - target) < 0) { }
        }
        __threadfence();
    }
    __syncthreads();
}

__device__ __forceinline__ float pml_b(int i)
{
    const double d0 = 3.0 * 1600.0 * log(1000.0) / (2.0 * PML_W * 4.0);
    double dd = 0.0;
    if (i < PML_W) {
        double a = (double)(PML_W - i) / PML_W;
        dd = d0 * a * a;
    } else if (i >= NG - PML_W) {
        double a = ((double)i - (NG - 1 - PML_W)) / PML_W;
        dd = d0 * a * a;
    }
    return (float)exp(-dd * 4.0e-4);
}

__device__ __forceinline__ float2 ld2(const float* __restrict__ p, int idx)
{
    return *reinterpret_cast<const float2*>(p + idx);
}
__device__ __forceinline__ void st2(float* __restrict__ p, int idx, float a, float b)
{
    *reinterpret_cast<float2*>(p + idx) = make_float2(a, b);
}

__global__ __launch_bounds__(TPB, 1) void sim_kernel(
    const float* __restrict__ lamb,
    const float* __restrict__ mu,
    const float* __restrict__ buoy,
    const float* __restrict__ amps,   // [NSHOT, NSRC, NT]
    const int*   __restrict__ sloc,   // [NSHOT, NSRC, 2]
    const int*   __restrict__ rloc,   // [NSHOT, NREC, 2]
    float* __restrict__ out)          // [NSHOT, NREC, NT-1]
{
    __shared__ float s_vy[NSHOT][EXT_R][EXT_C];
    __shared__ float s_vx[NSHOT][EXT_R][EXT_C];

    const int tid = threadIdx.x;
    const int blk = blockIdx.x;
    const int by0 = (blk / TCB) * TILE_R;
    const int bx0 = (blk % TCB) * TILE_C;
    const int rr = tid / NPR;            // 0..19 tile row
    const int pp = tid - rr * NPR;       // 0..19 pair within row
    const int y  = by0 + rr;
    const int x0 = bx0 + 2 * pp;
    unsigned ph = g_phase;

    // ---- core wrapped indices ----
    const int ym1 = (y + NG - 1) % NG, ym2 = (y + NG - 2) % NG;
    const int yp1 = (y + 1) % NG,      yp2 = (y + 2) % NG;
    const int row  = y   * NG;
    const int rym1 = ym1 * NG, rym2 = ym2 * NG;
    const int ryp1 = yp1 * NG, ryp2 = yp2 * NG;
    const int xm2c = (x0 == 0)      ? NG - 2 : x0 - 2;
    const int xp2c = (x0 == NG - 2) ? 0      : x0 + 2;
    const int o = row + x0;

    const float byv  = pml_b(y);
    const float bxv0 = pml_b(x0);
    const float bxv1 = pml_b(x0 + 1);
    const float2 bv2  = ld2(buoy, o);
    const float2 lam2 = ld2(lamb, o);
    const float2 mu2  = ld2(mu,   o);
    const float l2m0 = lam2.x + 2.0f * mu2.x;
    const float l2m1 = lam2.y + 2.0f * mu2.y;
    const bool ybord = (y < 2 || y >= NG - 2);
    const float mk0 = (ybord || x0     < 2 || x0     >= NG - 2) ? 0.0f : 1.0f;
    const float mk1 = (ybord || x0 + 1 < 2 || x0 + 1 >= NG - 2) ? 0.0f : 1.0f;

    // core source masks: bit s -> cell0, bit s+8 -> cell1
    unsigned smask[2] = {0u, 0u};
#pragma unroll
    for (int b = 0; b < NSHOT; b++)
#pragma unroll
        for (int s = 0; s < NSRC; s++) {
            int sy = sloc[(b*NSRC + s)*2], sx = sloc[(b*NSRC + s)*2 + 1];
            if (sy == y && sx == x0)     smask[b] |= 1u << s;
            if (sy == y && sx == x0 + 1) smask[b] |= 1u << (s + 8);
        }

    // receiver ownership (precomputed; overflow fallback keeps correctness)
    int rcode[8];
    int rcnt = 0;
    bool rovf = false;
    for (int e = 0; e < NSHOT * NREC; e++) {
        int ry = rloc[e*2], rx = rloc[e*2 + 1];
        if (ry == y && (rx == x0 || rx == x0 + 1)) {
            if (rcnt < 8) rcode[rcnt++] = e * 2 + (rx - x0);
            else rovf = true;
        }
    }

    // ---- ring cell setup (threads 0..239) ----
    const bool has_ring = (tid < NRING);
    int r_ey = 0, r_ex = 0, r_gy = 0, r_gx = 0;
    if (has_ring) {
        int k = tid;
        if (k < 80)       { r_ey = k / 40;              r_ex = 2 + (k % 40); }
        else if (k < 160) { r_ey = 22 + (k - 80) / 40;  r_ex = 2 + ((k - 80) % 40); }
        else if (k < 200) { r_ey = 2 + (k - 160) % 20;  r_ex = (k - 160) / 20; }
        else              { r_ey = 2 + (k - 200) % 20;  r_ex = 42 + (k - 200) / 20; }
        r_gy = (by0 + r_ey - 2 + NG) % NG;
        r_gx = (bx0 + r_ex - 2 + NG) % NG;
    }
    const int gro   = r_gy * NG;
    const int grym1 = ((r_gy + NG - 1) % NG) * NG;
    const int grym2 = ((r_gy + NG - 2) % NG) * NG;
    const int gryp1 = ((r_gy + 1) % NG) * NG;
    const int gryp2 = ((r_gy + 2) % NG) * NG;
    const int gxm1 = (r_gx + NG - 1) % NG, gxm2 = (r_gx + NG - 2) % NG;
    const int gxp1 = (r_gx + 1) % NG,      gxp2 = (r_gx + 2) % NG;
    const int ro = gro + r_gx;
    const float rbyv = pml_b(r_gy);
    const float rbxv = pml_b(r_gx);
    const float rbv  = buoy[ro];
    const float rmk  = (r_gy < 2 || r_gy >= NG-2 || r_gx < 2 || r_gx >= NG-2) ? 0.0f : 1.0f;
    unsigned rsmask[2] = {0u, 0u};
    if (has_ring) {
#pragma unroll
        for (int b = 0; b < NSHOT; b++)
#pragma unroll
            for (int s = 0; s < NSRC; s++)
                if (sloc[(b*NSRC + s)*2] == r_gy && sloc[(b*NSRC + s)*2 + 1] == r_gx)
                    rsmask[b] |= 1u << s;
    }

    // ---- register state ----
    float vy[2][2]  = {{0,0},{0,0}}, vx[2][2]  = {{0,0},{0,0}};
    float syy[2][2] = {{0,0},{0,0}}, sxy[2][2] = {{0,0},{0,0}}, sxx[2][2] = {{0,0},{0,0}};
    float m_vyy[2][2]  = {{0,0},{0,0}}, m_vyx[2][2]  = {{0,0},{0,0}};
    float m_vxy[2][2]  = {{0,0},{0,0}}, m_vxx[2][2]  = {{0,0},{0,0}};
    float m_syyy[2][2] = {{0,0},{0,0}}, m_sxyy[2][2] = {{0,0},{0,0}};
    float m_sxyx[2][2] = {{0,0},{0,0}}, m_sxxx[2][2] = {{0,0},{0,0}};
    float r_vy[2] = {0,0}, r_vx[2] = {0,0};
    float r_msyyy[2] = {0,0}, r_msxyy[2] = {0,0}, r_msxyx[2] = {0,0}, r_msxxx[2] = {0,0};

    // zero stress buffer 0 (read by step 0)
#pragma unroll
    for (int b = 0; b < NSHOT; b++) {
        int i = b * NS1 + o;
        st2(g_syy[0], i, 0.f, 0.f);
        st2(g_sxy[0], i, 0.f, 0.f);
        st2(g_sxx[0], i, 0.f, 0.f);
    }
    gbar(++ph);

    const float C1 = 1.125f;
    const float C2 = -1.0f / 24.0f;

#pragma unroll 1
    for (int t = 0; t < NT; t++) {
        const int p = t & 1;           // read buffer
        const int q = p ^ 1;           // write buffer
        const float* __restrict__ Syy = g_syy[p];
        const float* __restrict__ Sxy = g_sxy[p];
        const float* __restrict__ Sxx = g_sxx[p];

        // ================= velocity: core =================
#pragma unroll
        for (int b = 0; b < NSHOT; b++) {
            const int base = b * NS1;
            float d0, d1, m;

            float2 a_ym1 = ld2(Syy, base + rym1 + x0);
            float2 a_ym2 = ld2(Syy, base + rym2 + x0);
            float2 a_yp1 = ld2(Syy, base + ryp1 + x0);
            d0 = (C1*(syy[b][0] - a_ym1.x) + C2*(a_yp1.x - a_ym2.x)) * IDHF;
            d1 = (C1*(syy[b][1] - a_ym1.y) + C2*(a_yp1.y - a_ym2.y)) * IDHF;
            m = m_syyy[b][0]; m = byv*m + (byv-1.0f)*d0; m_syyy[b][0] = m;
            float ay0 = d0 + m;
            m = m_syyy[b][1]; m = byv*m + (byv-1.0f)*d1; m_syyy[b][1] = m;
            float ay1 = d1 + m;

            float2 u_xm = ld2(Sxy, base + row + xm2c);
            float2 u_xp = ld2(Sxy, base + row + xp2c);
            d0 = (C1*(sxy[b][1] - sxy[b][0]) + C2*(u_xp.x - u_xm.y)) * IDHF;
            d1 = (C1*(u_xp.x   - sxy[b][1]) + C2*(u_xp.y - sxy[b][0])) * IDHF;
            m = m_sxyx[b][0]; m = bxv0*m + (bxv0-1.0f)*d0; m_sxyx[b][0] = m;
            ay0 += d0 + m;
            m = m_sxyx[b][1]; m = bxv1*m + (bxv1-1.0f)*d1; m_sxyx[b][1] = m;
            ay1 += d1 + m;

            vy[b][0] += DTF * bv2.x * ay0;
            vy[b][1] += DTF * bv2.y * ay1;

            float2 w_xm = ld2(Sxx, base + row + xm2c);
            float2 w_xp = ld2(Sxx, base + row + xp2c);
            d0 = (C1*(sxx[b][0] - w_xm.y) + C2*(sxx[b][1] - w_xm.x)) * IDHF;
            d1 = (C1*(sxx[b][1] - sxx[b][0]) + C2*(w_xp.x - w_xm.y)) * IDHF;
            m = m_sxxx[b][0]; m = bxv0*m + (bxv0-1.0f)*d0; m_sxxx[b][0] = m;
            float ax0 = d0 + m;
            m = m_sxxx[b][1]; m = bxv1*m + (bxv1-1.0f)*d1; m_sxxx[b][1] = m;
            float ax1 = d1 + m;

            float2 s_yp1v = ld2(Sxy, base + ryp1 + x0);
            float2 s_yp2v = ld2(Sxy, base + ryp2 + x0);
            float2 s_ym1v = ld2(Sxy, base + rym1 + x0);
            d0 = (C1*(s_yp1v.x - sxy[b][0]) + C2*(s_yp2v.x - s_ym1v.x)) * IDHF;
            d1 = (C1*(s_yp1v.y - sxy[b][1]) + C2*(s_yp2v.y - s_ym1v.y)) * IDHF;
            m = m_sxyy[b][0]; m = byv*m + (byv-1.0f)*d0; m_sxyy[b][0] = m;
            ax0 += d0 + m;
            m = m_sxyy[b][1]; m = byv*m + (byv-1.0f)*d1; m_sxyy[b][1] = m;
            ax1 += d1 + m;

            vx[b][0] += DTF * bv2.x * ax0;
            vx[b][1] += DTF * bv2.y * ax1;

            if (smask[b]) {
#pragma unroll
                for (int s = 0; s < NSRC; s++) {
                    if (smask[b] & (1u << s))
                        vy[b][0] += DTF * amps[(b*NSRC + s)*NT + t] * bv2.x;
                    if (smask[b] & (1u << (s + 8)))
                        vy[b][1] += DTF * amps[(b*NSRC + s)*NT + t] * bv2.y;
                }
            }
            vy[b][0] *= mk0; vy[b][1] *= mk1;
            vx[b][0] *= mk0; vx[b][1] *= mk1;

            s_vy[b][2+rr][2+2*pp]   = vy[b][0];
            s_vy[b][2+rr][2+2*pp+1] = vy[b][1];
            s_vx[b][2+rr][2+2*pp]   = vx[b][0];
            s_vx[b][2+rr][2+2*pp+1] = vx[b][1];
        }

        // ================= velocity: ring =================
        if (has_ring) {
#pragma unroll
            for (int b = 0; b < NSHOT; b++) {
                const int base = b * NS1;
                float d, m;

                d = (C1*(Syy[base+ro] - Syy[base+grym1+r_gx])
                   + C2*(Syy[base+gryp1+r_gx] - Syy[base+grym2+r_gx])) * IDHF;
                m = r_msyyy[b]; m = rbyv*m + (rbyv-1.0f)*d; r_msyyy[b] = m;
                float ay = d + m;

                d = (C1*(Sxy[base+gro+gxp1] - Sxy[base+ro])
                   + C2*(Sxy[base+gro+gxp2] - Sxy[base+gro+gxm1])) * IDHF;
                m = r_msxyx[b]; m = rbxv*m + (rbxv-1.0f)*d; r_msxyx[b] = m;
                ay += d + m;

                r_vy[b] += DTF * rbv * ay;

                d = (C1*(Sxx[base+ro] - Sxx[base+gro+gxm1])
                   + C2*(Sxx[base+gro+gxp1] - Sxx[base+gro+gxm2])) * IDHF;
                m = r_msxxx[b]; m = rbxv*m + (rbxv-1.0f)*d; r_msxxx[b] = m;
                float ax = d + m;

                d = (C1*(Sxy[base+gryp1+r_gx] - Sxy[base+ro])
                   + C2*(Sxy[base+gryp2+r_gx] - Sxy[base+grym1+r_gx])) * IDHF;
                m = r_msxyy[b]; m = rbyv*m + (rbyv-1.0f)*d; r_msxyy[b] = m;
                ax += d + m;

                r_vx[b] += DTF * rbv * ax;

                if (rsmask[b]) {
#pragma unroll
                    for (int s = 0; s < NSRC; s++)
                        if (rsmask[b] & (1u << s))
                            r_vy[b] += DTF * amps[(b*NSRC + s)*NT + t] * rbv;
                }
                r_vy[b] *= rmk;
                r_vx[b] *= rmk;
                s_vy[b][r_ey][r_ex] = r_vy[b];
                s_vx[b][r_ey][r_ex] = r_vx[b];
            }
        }

        // receivers (owner records from registers; no cross-block read)
        if (rovf) {
            for (int e = 0; e < NSHOT * NREC; e++) {
                int ry = rloc[e*2], rx = rloc[e*2 + 1];
                if (ry == y && (rx == x0 || rx == x0 + 1)) {
                    int b = e / NREC;
                    g_recs[t*(NSHOT*NREC) + e] = vy[b][rx - x0];
                }
            }
        } else {
            for (int i = 0; i < rcnt; i++) {
                int e = rcode[i] >> 1, c = rcode[i] & 1;
                g_recs[t*(NSHOT*NREC) + e] = vy[e / NREC][c];
            }
        }

        __syncthreads();

        // ================= stress: core (SMEM taps) =================
        {
            const int sy = 2 + rr, sx = 2 + 2*pp;
#pragma unroll
            for (int b = 0; b < NSHOT; b++) {
                const int base = b * NS1;
                float d0, d1, m;

                // e1 = Dy+(vy)
                d0 = (C1*(s_vy[b][sy+1][sx]   - vy[b][0])
                    + C2*(s_vy[b][sy+2][sx]   - s_vy[b][sy-1][sx])) * IDHF;
                d1 = (C1*(s_vy[b][sy+1][sx+1] - vy[b][1])
                    + C2*(s_vy[b][sy+2][sx+1] - s_vy[b][sy-1][sx+1])) * IDHF;
                m = m_vyy[b][0]; m = byv*m + (byv-1.0f)*d0; m_vyy[b][0] = m;
                float e10 = d0 + m;
                m = m_vyy[b][1]; m = byv*m + (byv-1.0f)*d1; m_vyy[b][1] = m;
                float e11 = d1 + m;

                // e2 = Dx-(vx)
                float vxm1 = s_vx[b][sy][sx-1], vxm2 = s_vx[b][sy][sx-2];
                float vxp2 = s_vx[b][sy][sx+2];
                d0 = (C1*(vx[b][0] - vxm1) + C2*(vx[b][1] - vxm2)) * IDHF;
                d1 = (C1*(vx[b][1] - vx[b][0]) + C2*(vxp2 - vxm1)) * IDHF;
                m = m_vxx[b][0]; m = bxv0*m + (bxv0-1.0f)*d0; m_vxx[b][0] = m;
                float e20 = d0 + m;
                m = m_vxx[b][1]; m = bxv1*m + (bxv1-1.0f)*d1; m_vxx[b][1] = m;
                float e21 = d1 + m;

                syy[b][0] = (syy[b][0] + DTF*(l2m0*e10 + lam2.x*e20)) * mk0;
                syy[b][1] = (syy[b][1] + DTF*(l2m1*e11 + lam2.y*e21)) * mk1;
                sxx[b][0] = (sxx[b][0] + DTF*(l2m0*e20 + lam2.x*e10)) * mk0;
                sxx[b][1] = (sxx[b][1] + DTF*(l2m1*e21 + lam2.y*e11)) * mk1;

                // g = Dx+(vy)
                float vym1 = s_vy[b][sy][sx-1];
                float vyp2 = s_vy[b][sy][sx+2], vyp3 = s_vy[b][sy][sx+3];
                d0 = (C1*(vy[b][1] - vy[b][0]) + C2*(vyp2 - vym1)) * IDHF;
                d1 = (C1*(vyp2 - vy[b][1]) + C2*(vyp3 - vy[b][0])) * IDHF;
                m = m_vyx[b][0]; m = bxv0*m + (bxv0-1.0f)*d0; m_vyx[b][0] = m;
                float g0 = d0 + m;
                m = m_vyx[b][1]; m = bxv1*m + (bxv1-1.0f)*d1; m_vyx[b][1] = m;
                float g1 = d1 + m;

                // g += Dy-(vx)
                d0 = (C1*(vx[b][0] - s_vx[b][sy-1][sx])
                    + C2*(s_vx[b][sy+1][sx] - s_vx[b][sy-2][sx])) * IDHF;
                d1 = (C1*(vx[b][1] - s_vx[b][sy-1][sx+1])
                    + C2*(s_vx[b][sy+1][sx+1] - s_vx[b][sy-2][sx+1])) * IDHF;
                m = m_vxy[b][0]; m = byv*m + (byv-1.0f)*d0; m_vxy[b][0] = m;
                g0 += d0 + m;
                m = m_vxy[b][1]; m = byv*m + (byv-1.0f)*d1; m_vxy[b][1] = m;
                g1 += d1 + m;

                sxy[b][0] = (sxy[b][0] + DTF*mu2.x*g0) * mk0;
                sxy[b][1] = (sxy[b][1] + DTF*mu2.y*g1) * mk1;

                st2(g_syy[q], base + o, syy[b][0], syy[b][1]);
                st2(g_sxy[q], base + o, sxy[b][0], sxy[b][1]);
                st2(g_sxx[q], base + o, sxx[b][0], sxx[b][1]);
            }
        }
        gbar(++ph);
    }

    // ---------------- finalize ----------------
    const int gtid = blk * TPB + tid;
    const int total = NSHOT * NREC * (NT - 1);
    if (gtid < total) {
        int t = gtid % (NT - 1);
        int e = gtid / (NT - 1);   // e = b*NREC + r
        out[e * (NT - 1) + t] = 0.5f * (g_recs[(t + 1)*(NSHOT*NREC) + e]
                                      + g_recs[t      *(NSHOT*NREC) + e]);
    }
}

extern "C" void kernel_launch(void* const* d_in, const int* in_sizes, int n_in,
                              void* d_out, int out_size)
{
    const float* lamb = (const float*)d_in[0];
    const float* mu   = (const float*)d_in[1];
    const float* buoy = (const float*)d_in[2];
    const float* amps = (const float*)d_in[3];
    const int*   sloc = (const int*)d_in[4];
    const int*   rloc = (const int*)d_in[5];
    float* out = (float*)d_out;

    sim_kernel<<<NBLK, TPB>>>(lamb, mu, buoy, amps, sloc, rloc, out);
}

// round 6
// speedup vs baseline: 1.5545x; 1.2294x over previous
#include <cuda_runtime.h>
#include <math.h>

#define NG     320
#define NS1    (NG*NG)
#define NSHOT  2
#define NSRC   8
#define NREC   96
#define NT     160
#define PML_W  20
#define NBLK   128
#define TPB    400
#define TILE_R 20
#define TILE_C 40
#define TCB    8            // block-grid cols (320/40)
#define TRB    16           // block-grid rows (320/20)
#define NPR    (TILE_C/2)   // 20 pairs per tile row
#define NRING  240
#define EXT_R  24
#define EXT_C  45           // 44 used + 1 pad
#define IDHF   0.25f
#define DTF    4.0e-4f

// Triple-buffered global stress. Velocity lives only in registers/SMEM.
__device__ float g_syy[3][NSHOT*NS1];
__device__ float g_sxy[3][NSHOT*NS1];
__device__ float g_sxx[3][NSHOT*NS1];
__device__ float g_recs[NT*NSHOT*NREC];

// per-block step flags, one 128B line each; monotonic across graph replays
__device__ __align__(128) unsigned g_flag[NBLK*32];
__device__ __align__(128) unsigned g_count = 0;
__device__ __align__(128) volatile unsigned g_phase = 0;

// one-shot global barrier (used only before finalize)
__device__ __forceinline__ void gbar(unsigned target)
{
    __syncthreads();
    if (threadIdx.x == 0) {
        __threadfence();
        if (atomicAdd(&g_count, 1u) == NBLK - 1) {
            g_count = 0;
            __threadfence();
            g_phase = target;
        } else {
            while ((int)(g_phase - target) < 0) { }
        }
        __threadfence();
    }
    __syncthreads();
}

__device__ __forceinline__ unsigned ld_acq(const unsigned* p)
{
    unsigned v;
    asm volatile("ld.acquire.gpu.global.u32 %0, [%1];" : "=r"(v) : "l"(p) : "memory");
    return v;
}
__device__ __forceinline__ void red_add(unsigned* p)
{
    asm volatile("red.global.add.u32 [%0], %1;" :: "l"(p), "r"(1u) : "memory");
}

__device__ __forceinline__ float pml_b(int i)
{
    const double d0 = 3.0 * 1600.0 * log(1000.0) / (2.0 * PML_W * 4.0);
    double dd = 0.0;
    if (i < PML_W) {
        double a = (double)(PML_W - i) / PML_W;
        dd = d0 * a * a;
    } else if (i >= NG - PML_W) {
        double a = ((double)i - (NG - 1 - PML_W)) / PML_W;
        dd = d0 * a * a;
    }
    return (float)exp(-dd * 4.0e-4);
}

__device__ __forceinline__ float2 ld2(const float* __restrict__ p, int idx)
{
    return *reinterpret_cast<const float2*>(p + idx);
}
__device__ __forceinline__ void st2(float* __restrict__ p, int idx, float a, float b)
{
    *reinterpret_cast<float2*>(p + idx) = make_float2(a, b);
}

__global__ __launch_bounds__(TPB, 1) void sim_kernel(
    const float* __restrict__ lamb,
    const float* __restrict__ mu,
    const float* __restrict__ buoy,
    const float* __restrict__ amps,   // [NSHOT, NSRC, NT]
    const int*   __restrict__ sloc,   // [NSHOT, NSRC, 2]
    const int*   __restrict__ rloc,   // [NSHOT, NREC, 2]
    float* __restrict__ out)          // [NSHOT, NREC, NT-1]
{
    __shared__ float s_vy[NSHOT][EXT_R][EXT_C];
    __shared__ float s_vx[NSHOT][EXT_R][EXT_C];

    const int tid = threadIdx.x;
    const int blk = blockIdx.x;
    const int by0 = (blk / TCB) * TILE_R;
    const int bx0 = (blk % TCB) * TILE_C;
    const int rr = tid / NPR;            // 0..19
    const int pp = tid - rr * NPR;       // 0..19
    const int y  = by0 + rr;
    const int x0 = bx0 + 2 * pp;
    unsigned ph = g_phase;
    const unsigned F = g_flag[blk * 32];   // equal across blocks at entry

    // 8 torus neighbors in the 16x8 block grid
    int nbid = -1;
    if (tid < 8) {
        const int dR[8] = {-1,-1,-1, 0, 0, 1, 1, 1};
        const int dC[8] = {-1, 0, 1,-1, 1,-1, 0, 1};
        int bR = blk / TCB, bC = blk % TCB;
        int nR = (bR + dR[tid] + TRB) % TRB;
        int nC = (bC + dC[tid] + TCB) % TCB;
        nbid = nR * TCB + nC;
    }

    // ---- core wrapped indices ----
    const int ym1 = (y + NG - 1) % NG, ym2 = (y + NG - 2) % NG;
    const int yp1 = (y + 1) % NG,      yp2 = (y + 2) % NG;
    const int row  = y   * NG;
    const int rym1 = ym1 * NG, rym2 = ym2 * NG;
    const int ryp1 = yp1 * NG, ryp2 = yp2 * NG;
    const int xm2c = (x0 == 0)      ? NG - 2 : x0 - 2;
    const int xp2c = (x0 == NG - 2) ? 0      : x0 + 2;
    const int o = row + x0;

    const float byv  = pml_b(y);
    const float bxv0 = pml_b(x0);
    const float bxv1 = pml_b(x0 + 1);
    const float2 bv2  = ld2(buoy, o);
    const float2 lam2 = ld2(lamb, o);
    const float2 mu2  = ld2(mu,   o);
    const float l2m0 = lam2.x + 2.0f * mu2.x;
    const float l2m1 = lam2.y + 2.0f * mu2.y;
    const bool ybord = (y < 2 || y >= NG - 2);
    const float mk0 = (ybord || x0     < 2 || x0     >= NG - 2) ? 0.0f : 1.0f;
    const float mk1 = (ybord || x0 + 1 < 2 || x0 + 1 >= NG - 2) ? 0.0f : 1.0f;

    unsigned smask[2] = {0u, 0u};
#pragma unroll
    for (int b = 0; b < NSHOT; b++)
#pragma unroll
        for (int s = 0; s < NSRC; s++) {
            int sy = sloc[(b*NSRC + s)*2], sx = sloc[(b*NSRC + s)*2 + 1];
            if (sy == y && sx == x0)     smask[b] |= 1u << s;
            if (sy == y && sx == x0 + 1) smask[b] |= 1u << (s + 8);
        }

    int rcode[8];
    int rcnt = 0;
    bool rovf = false;
    for (int e = 0; e < NSHOT * NREC; e++) {
        int ry = rloc[e*2], rx = rloc[e*2 + 1];
        if (ry == y && (rx == x0 || rx == x0 + 1)) {
            if (rcnt < 8) rcode[rcnt++] = e * 2 + (rx - x0);
            else rovf = true;
        }
    }

    // ---- ring cells (threads 0..239): cross-shaped 2-wide ring ----
    const bool has_ring = (tid < NRING);
    int r_ey = 0, r_ex = 0, r_gy = 0, r_gx = 0;
    if (has_ring) {
        int k = tid;
        if (k < 80)       { r_ey = k / 40;              r_ex = 2 + (k % 40); }
        else if (k < 160) { r_ey = 22 + (k - 80) / 40;  r_ex = 2 + ((k - 80) % 40); }
        else if (k < 200) { r_ey = 2 + (k - 160) % 20;  r_ex = (k - 160) / 20; }
        else              { r_ey = 2 + (k - 200) % 20;  r_ex = 42 + (k - 200) / 20; }
        r_gy = (by0 + r_ey - 2 + NG) % NG;
        r_gx = (bx0 + r_ex - 2 + NG) % NG;
    }
    const int gro   = r_gy * NG;
    const int grym1 = ((r_gy + NG - 1) % NG) * NG;
    const int grym2 = ((r_gy + NG - 2) % NG) * NG;
    const int gryp1 = ((r_gy + 1) % NG) * NG;
    const int gryp2 = ((r_gy + 2) % NG) * NG;
    const int gxm1 = (r_gx + NG - 1) % NG, gxm2 = (r_gx + NG - 2) % NG;
    const int gxp1 = (r_gx + 1) % NG,      gxp2 = (r_gx + 2) % NG;
    const int ro = gro + r_gx;
    const float rbyv = pml_b(r_gy);
    const float rbxv = pml_b(r_gx);
    const float rbv  = buoy[ro];
    const float rmk  = (r_gy < 2 || r_gy >= NG-2 || r_gx < 2 || r_gx >= NG-2) ? 0.0f : 1.0f;
    unsigned rsmask[2] = {0u, 0u};
    if (has_ring) {
#pragma unroll
        for (int b = 0; b < NSHOT; b++)
#pragma unroll
            for (int s = 0; s < NSRC; s++)
                if (sloc[(b*NSRC + s)*2] == r_gy && sloc[(b*NSRC + s)*2 + 1] == r_gx)
                    rsmask[b] |= 1u << s;
    }

    // ---- register state ----
    float vy[2][2]  = {{0,0},{0,0}}, vx[2][2]  = {{0,0},{0,0}};
    float syy[2][2] = {{0,0},{0,0}}, sxy[2][2] = {{0,0},{0,0}}, sxx[2][2] = {{0,0},{0,0}};
    float m_vyy[2][2]  = {{0,0},{0,0}}, m_vyx[2][2]  = {{0,0},{0,0}};
    float m_vxy[2][2]  = {{0,0},{0,0}}, m_vxx[2][2]  = {{0,0},{0,0}};
    float m_syyy[2][2] = {{0,0},{0,0}}, m_sxyy[2][2] = {{0,0},{0,0}};
    float m_sxyx[2][2] = {{0,0},{0,0}}, m_sxxx[2][2] = {{0,0},{0,0}};
    float r_vy[2] = {0,0}, r_vx[2] = {0,0};
    float r_msyyy[2] = {0,0}, r_msxyy[2] = {0,0}, r_msxyx[2] = {0,0}, r_msxxx[2] = {0,0};

    // zero stress buffer 2 on own core: read as str(-1) by step 0
#pragma unroll
    for (int b = 0; b < NSHOT; b++) {
        int i = b * NS1 + o;
        st2(g_syy[2], i, 0.f, 0.f);
        st2(g_sxy[2], i, 0.f, 0.f);
        st2(g_sxx[2], i, 0.f, 0.f);
    }
    __syncthreads();
    if (tid == 0) { __threadfence(); red_add(&g_flag[blk * 32]); }   // flag = F+1

    const float C1 = 1.125f;
    const float C2 = -1.0f / 24.0f;

#pragma unroll 1
    for (int t = 0; t < NT; t++) {
        // wait for 8 neighbors to have completed step t-1 (flag >= F+1+t)
        if (tid < 8) {
            const unsigned tgt = F + 1u + (unsigned)t;
            const unsigned* fp = &g_flag[nbid * 32];
            while ((int)(ld_acq(fp) - tgt) < 0) { }
        }
        __syncthreads();

        const int p = (t + 2) % 3;     // read buffer: str(t-1)
        const int q = t % 3;           // write buffer: str(t)
        const float* __restrict__ Syy = g_syy[p];
        const float* __restrict__ Sxy = g_sxy[p];
        const float* __restrict__ Sxx = g_sxx[p];

        // ================= velocity: core =================
#pragma unroll
        for (int b = 0; b < NSHOT; b++) {
            const int base = b * NS1;
            float d0, d1, m;

            float2 a_ym1 = ld2(Syy, base + rym1 + x0);
            float2 a_ym2 = ld2(Syy, base + rym2 + x0);
            float2 a_yp1 = ld2(Syy, base + ryp1 + x0);
            d0 = (C1*(syy[b][0] - a_ym1.x) + C2*(a_yp1.x - a_ym2.x)) * IDHF;
            d1 = (C1*(syy[b][1] - a_ym1.y) + C2*(a_yp1.y - a_ym2.y)) * IDHF;
            m = m_syyy[b][0]; m = byv*m + (byv-1.0f)*d0; m_syyy[b][0] = m;
            float ay0 = d0 + m;
            m = m_syyy[b][1]; m = byv*m + (byv-1.0f)*d1; m_syyy[b][1] = m;
            float ay1 = d1 + m;

            float2 u_xm = ld2(Sxy, base + row + xm2c);
            float2 u_xp = ld2(Sxy, base + row + xp2c);
            d0 = (C1*(sxy[b][1] - sxy[b][0]) + C2*(u_xp.x - u_xm.y)) * IDHF;
            d1 = (C1*(u_xp.x   - sxy[b][1]) + C2*(u_xp.y - sxy[b][0])) * IDHF;
            m = m_sxyx[b][0]; m = bxv0*m + (bxv0-1.0f)*d0; m_sxyx[b][0] = m;
            ay0 += d0 + m;
            m = m_sxyx[b][1]; m = bxv1*m + (bxv1-1.0f)*d1; m_sxyx[b][1] = m;
            ay1 += d1 + m;

            vy[b][0] += DTF * bv2.x * ay0;
            vy[b][1] += DTF * bv2.y * ay1;

            float2 w_xm = ld2(Sxx, base + row + xm2c);
            float2 w_xp = ld2(Sxx, base + row + xp2c);
            d0 = (C1*(sxx[b][0] - w_xm.y) + C2*(sxx[b][1] - w_xm.x)) * IDHF;
            d1 = (C1*(sxx[b][1] - sxx[b][0]) + C2*(w_xp.x - w_xm.y)) * IDHF;
            m = m_sxxx[b][0]; m = bxv0*m + (bxv0-1.0f)*d0; m_sxxx[b][0] = m;
            float ax0 = d0 + m;
            m = m_sxxx[b][1]; m = bxv1*m + (bxv1-1.0f)*d1; m_sxxx[b][1] = m;
            float ax1 = d1 + m;

            float2 s_yp1v = ld2(Sxy, base + ryp1 + x0);
            float2 s_yp2v = ld2(Sxy, base + ryp2 + x0);
            float2 s_ym1v = ld2(Sxy, base + rym1 + x0);
            d0 = (C1*(s_yp1v.x - sxy[b][0]) + C2*(s_yp2v.x - s_ym1v.x)) * IDHF;
            d1 = (C1*(s_yp1v.y - sxy[b][1]) + C2*(s_yp2v.y - s_ym1v.y)) * IDHF;
            m = m_sxyy[b][0]; m = byv*m + (byv-1.0f)*d0; m_sxyy[b][0] = m;
            ax0 += d0 + m;
            m = m_sxyy[b][1]; m = byv*m + (byv-1.0f)*d1; m_sxyy[b][1] = m;
            ax1 += d1 + m;

            vx[b][0] += DTF * bv2.x * ax0;
            vx[b][1] += DTF * bv2.y * ax1;

            if (smask[b]) {
#pragma unroll
                for (int s = 0; s < NSRC; s++) {
                    if (smask[b] & (1u << s))
                        vy[b][0] += DTF * amps[(b*NSRC + s)*NT + t] * bv2.x;
                    if (smask[b] & (1u << (s + 8)))
                        vy[b][1] += DTF * amps[(b*NSRC + s)*NT + t] * bv2.y;
                }
            }
            vy[b][0] *= mk0; vy[b][1] *= mk1;
            vx[b][0] *= mk0; vx[b][1] *= mk1;

            s_vy[b][2+rr][2+2*pp]   = vy[b][0];
            s_vy[b][2+rr][2+2*pp+1] = vy[b][1];
            s_vx[b][2+rr][2+2*pp]   = vx[b][0];
            s_vx[b][2+rr][2+2*pp+1] = vx[b][1];
        }

        // ================= velocity: ring =================
        if (has_ring) {
#pragma unroll
            for (int b = 0; b < NSHOT; b++) {
                const int base = b * NS1;
                float d, m;

                d = (C1*(Syy[base+ro] - Syy[base+grym1+r_gx])
                   + C2*(Syy[base+gryp1+r_gx] - Syy[base+grym2+r_gx])) * IDHF;
                m = r_msyyy[b]; m = rbyv*m + (rbyv-1.0f)*d; r_msyyy[b] = m;
                float ay = d + m;

                d = (C1*(Sxy[base+gro+gxp1] - Sxy[base+ro])
                   + C2*(Sxy[base+gro+gxp2] - Sxy[base+gro+gxm1])) * IDHF;
                m = r_msxyx[b]; m = rbxv*m + (rbxv-1.0f)*d; r_msxyx[b] = m;
                ay += d + m;

                r_vy[b] += DTF * rbv * ay;

                d = (C1*(Sxx[base+ro] - Sxx[base+gro+gxm1])
                   + C2*(Sxx[base+gro+gxp1] - Sxx[base+gro+gxm2])) * IDHF;
                m = r_msxxx[b]; m = rbxv*m + (rbxv-1.0f)*d; r_msxxx[b] = m;
                float ax = d + m;

                d = (C1*(Sxy[base+gryp1+r_gx] - Sxy[base+ro])
                   + C2*(Sxy[base+gryp2+r_gx] - Sxy[base+grym1+r_gx])) * IDHF;
                m = r_msxyy[b]; m = rbyv*m + (rbyv-1.0f)*d; r_msxyy[b] = m;
                ax += d + m;

                r_vx[b] += DTF * rbv * ax;

                if (rsmask[b]) {
#pragma unroll
                    for (int s = 0; s < NSRC; s++)
                        if (rsmask[b] & (1u << s))
                            r_vy[b] += DTF * amps[(b*NSRC + s)*NT + t] * rbv;
                }
                r_vy[b] *= rmk;
                r_vx[b] *= rmk;
                s_vy[b][r_ey][r_ex] = r_vy[b];
                s_vx[b][r_ey][r_ex] = r_vx[b];
            }
        }

        // receivers (owner records from registers)
        if (rovf) {
            for (int e = 0; e < NSHOT * NREC; e++) {
                int ry = rloc[e*2], rx = rloc[e*2 + 1];
                if (ry == y && (rx == x0 || rx == x0 + 1)) {
                    int b = e / NREC;
                    g_recs[t*(NSHOT*NREC) + e] = vy[b][rx - x0];
                }
            }
        } else {
            for (int i = 0; i < rcnt; i++) {
                int e = rcode[i] >> 1, c = rcode[i] & 1;
                g_recs[t*(NSHOT*NREC) + e] = vy[e / NREC][c];
            }
        }

        __syncthreads();

        // ================= stress: core (SMEM taps) =================
        {
            const int sy = 2 + rr, sx = 2 + 2*pp;
#pragma unroll
            for (int b = 0; b < NSHOT; b++) {
                const int base = b * NS1;
                float d0, d1, m;

                d0 = (C1*(s_vy[b][sy+1][sx]   - vy[b][0])
                    + C2*(s_vy[b][sy+2][sx]   - s_vy[b][sy-1][sx])) * IDHF;
                d1 = (C1*(s_vy[b][sy+1][sx+1] - vy[b][1])
                    + C2*(s_vy[b][sy+2][sx+1] - s_vy[b][sy-1][sx+1])) * IDHF;
                m = m_vyy[b][0]; m = byv*m + (byv-1.0f)*d0; m_vyy[b][0] = m;
                float e10 = d0 + m;
                m = m_vyy[b][1]; m = byv*m + (byv-1.0f)*d1; m_vyy[b][1] = m;
                float e11 = d1 + m;

                float vxm1 = s_vx[b][sy][sx-1], vxm2 = s_vx[b][sy][sx-2];
                float vxp2 = s_vx[b][sy][sx+2];
                d0 = (C1*(vx[b][0] - vxm1) + C2*(vx[b][1] - vxm2)) * IDHF;
                d1 = (C1*(vx[b][1] - vx[b][0]) + C2*(vxp2 - vxm1)) * IDHF;
                m = m_vxx[b][0]; m = bxv0*m + (bxv0-1.0f)*d0; m_vxx[b][0] = m;
                float e20 = d0 + m;
                m = m_vxx[b][1]; m = bxv1*m + (bxv1-1.0f)*d1; m_vxx[b][1] = m;
                float e21 = d1 + m;

                syy[b][0] = (syy[b][0] + DTF*(l2m0*e10 + lam2.x*e20)) * mk0;
                syy[b][1] = (syy[b][1] + DTF*(l2m1*e11 + lam2.y*e21)) * mk1;
                sxx[b][0] = (sxx[b][0] + DTF*(l2m0*e20 + lam2.x*e10)) * mk0;
                sxx[b][1] = (sxx[b][1] + DTF*(l2m1*e21 + lam2.y*e11)) * mk1;

                float vym1 = s_vy[b][sy][sx-1];
                float vyp2 = s_vy[b][sy][sx+2], vyp3 = s_vy[b][sy][sx+3];
                d0 = (C1*(vy[b][1] - vy[b][0]) + C2*(vyp2 - vym1)) * IDHF;
                d1 = (C1*(vyp2 - vy[b][1]) + C2*(vyp3 - vy[b][0])) * IDHF;
                m = m_vyx[b][0]; m = bxv0*m + (bxv0-1.0f)*d0; m_vyx[b][0] = m;
                float g0 = d0 + m;
                m = m_vyx[b][1]; m = bxv1*m + (bxv1-1.0f)*d1; m_vyx[b][1] = m;
                float g1 = d1 + m;

                d0 = (C1*(vx[b][0] - s_vx[b][sy-1][sx])
                    + C2*(s_vx[b][sy+1][sx] - s_vx[b][sy-2][sx])) * IDHF;
                d1 = (C1*(vx[b][1] - s_vx[b][sy-1][sx+1])
                    + C2*(s_vx[b][sy+1][sx+1] - s_vx[b][sy-2][sx+1])) * IDHF;
                m = m_vxy[b][0]; m = byv*m + (byv-1.0f)*d0; m_vxy[b][0] = m;
                g0 += d0 + m;
                m = m_vxy[b][1]; m = byv*m + (byv-1.0f)*d1; m_vxy[b][1] = m;
                g1 += d1 + m;

                sxy[b][0] = (sxy[b][0] + DTF*mu2.x*g0) * mk0;
                sxy[b][1] = (sxy[b][1] + DTF*mu2.y*g1) * mk1;

                st2(g_syy[q], base + o, syy[b][0], syy[b][1]);
                st2(g_sxy[q], base + o, sxy[b][0], sxy[b][1]);
                st2(g_sxx[q], base + o, sxx[b][0], sxx[b][1]);
            }
        }

        // publish step t completion
        __syncthreads();
        if (tid == 0) { __threadfence(); red_add(&g_flag[blk * 32]); }
    }

    // ---------------- finalize (needs all blocks' g_recs) ----------------
    gbar(ph + 1);
    const int gtid = blk * TPB + tid;
    const int total = NSHOT * NREC * (NT - 1);
    if (gtid < total) {
        int t = gtid % (NT - 1);
        int e = gtid / (NT - 1);
        out[e * (NT - 1) + t] = 0.5f * (g_recs[(t + 1)*(NSHOT*NREC) + e]
                                      + g_recs[t      *(NSHOT*NREC) + e]);
    }
}

extern "C" void kernel_launch(void* const* d_in, const int* in_sizes, int n_in,
                              void* d_out, int out_size)
{
    const float* lamb = (const float*)d_in[0];
    const float* mu   = (const float*)d_in[1];
    const float* buoy = (const float*)d_in[2];
    const float* amps = (const float*)d_in[3];
    const int*   sloc = (const int*)d_in[4];
    const int*   rloc = (const int*)d_in[5];
    float* out = (float*)d_out;

    sim_kernel<<<NBLK, TPB>>>(lamb, mu, buoy, amps, sloc, rloc, out);
}

// round 7
// speedup vs baseline: 1.6213x; 1.0429x over previous
#include <cuda_runtime.h>
#include <math.h>

#define NG     320
#define NS1    (NG*NG)
#define NSHOT  2
#define NSRC   8
#define NREC   96
#define NT     160
#define PML_W  20
#define NBLK   256          // 128 tiles x 2 shots
#define NTILE  128
#define TPB    400
#define TILE_R 20
#define TILE_C 40
#define TCB    8            // tile-grid cols (320/40)
#define TRB    16           // tile-grid rows (320/20)
#define NPR    (TILE_C/2)   // 20 pairs per tile row
#define NRING  240
#define EXT_R  24
#define EXT_C  45           // 44 used + 1 pad
#define IDHF   0.25f
#define DTF    4.0e-4f

// Triple-buffered global stress. Velocity lives only in registers/SMEM.
__device__ float g_syy[3][NSHOT*NS1];
__device__ float g_sxy[3][NSHOT*NS1];
__device__ float g_sxx[3][NSHOT*NS1];
__device__ float g_recs[NT*NSHOT*NREC];

// per-block step flags, one 128B line each; monotonic across graph replays
__device__ __align__(128) unsigned g_flag[NBLK*32];
__device__ __align__(128) unsigned g_count = 0;
__device__ __align__(128) volatile unsigned g_phase = 0;

// one-shot global barrier (used only before finalize)
__device__ __forceinline__ void gbar(unsigned target)
{
    __syncthreads();
    if (threadIdx.x == 0) {
        __threadfence();
        if (atomicAdd(&g_count, 1u) == NBLK - 1) {
            g_count = 0;
            __threadfence();
            g_phase = target;
        } else {
            while ((int)(g_phase - target) < 0) { }
        }
        __threadfence();
    }
    __syncthreads();
}

__device__ __forceinline__ unsigned ld_acq(const unsigned* p)
{
    unsigned v;
    asm volatile("ld.acquire.gpu.global.u32 %0, [%1];" : "=r"(v) : "l"(p) : "memory");
    return v;
}
__device__ __forceinline__ void red_add(unsigned* p)
{
    asm volatile("red.global.add.u32 [%0], %1;" :: "l"(p), "r"(1u) : "memory");
}

__device__ __forceinline__ float pml_b(int i)
{
    const double d0 = 3.0 * 1600.0 * log(1000.0) / (2.0 * PML_W * 4.0);
    double dd = 0.0;
    if (i < PML_W) {
        double a = (double)(PML_W - i) / PML_W;
        dd = d0 * a * a;
    } else if (i >= NG - PML_W) {
        double a = ((double)i - (NG - 1 - PML_W)) / PML_W;
        dd = d0 * a * a;
    }
    return (float)exp(-dd * 4.0e-4);
}

__device__ __forceinline__ float2 ld2(const float* __restrict__ p, int idx)
{
    return *reinterpret_cast<const float2*>(p + idx);
}
__device__ __forceinline__ void st2(float* __restrict__ p, int idx, float a, float b)
{
    *reinterpret_cast<float2*>(p + idx) = make_float2(a, b);
}

__global__ __launch_bounds__(TPB, 2) void sim_kernel(
    const float* __restrict__ lamb,
    const float* __restrict__ mu,
    const float* __restrict__ buoy,
    const float* __restrict__ amps,   // [NSHOT, NSRC, NT]
    const int*   __restrict__ sloc,   // [NSHOT, NSRC, 2]
    const int*   __restrict__ rloc,   // [NSHOT, NREC, 2]
    float* __restrict__ out)          // [NSHOT, NREC, NT-1]
{
    __shared__ float s_vy[EXT_R][EXT_C];
    __shared__ float s_vx[EXT_R][EXT_C];

    const int tid  = threadIdx.x;
    const int blk  = blockIdx.x;
    const int shot = blk & 1;           // shot handled by this block
    const int tile = blk >> 1;          // 0..127
    const int by0 = (tile / TCB) * TILE_R;
    const int bx0 = (tile % TCB) * TILE_C;
    const int rr = tid / NPR;            // 0..19
    const int pp = tid - rr * NPR;       // 0..19
    const int y  = by0 + rr;
    const int x0 = bx0 + 2 * pp;
    const int base = shot * NS1;
    unsigned ph = g_phase;
    const unsigned F = g_flag[blk * 32];   // equal across blocks at entry

    // 8 torus neighbors (same shot) in the 16x8 tile grid
    int nbid = -1;
    if (tid < 8) {
        const int dR[8] = {-1,-1,-1, 0, 0, 1, 1, 1};
        const int dC[8] = {-1, 0, 1,-1, 1,-1, 0, 1};
        int bR = tile / TCB, bC = tile % TCB;
        int nR = (bR + dR[tid] + TRB) % TRB;
        int nC = (bC + dC[tid] + TCB) % TCB;
        nbid = ((nR * TCB + nC) << 1) | shot;
    }

    // ---- core wrapped indices ----
    const int ym1 = (y + NG - 1) % NG, ym2 = (y + NG - 2) % NG;
    const int yp1 = (y + 1) % NG,      yp2 = (y + 2) % NG;
    const int row  = y   * NG;
    const int rym1 = ym1 * NG, rym2 = ym2 * NG;
    const int ryp1 = yp1 * NG, ryp2 = yp2 * NG;
    const int xm2c = (x0 == 0)      ? NG - 2 : x0 - 2;
    const int xp2c = (x0 == NG - 2) ? 0      : x0 + 2;
    const int o = row + x0;

    const float byv  = pml_b(y);
    const float bxv0 = pml_b(x0);
    const float bxv1 = pml_b(x0 + 1);
    const float2 bv2  = ld2(buoy, o);
    const float2 lam2 = ld2(lamb, o);
    const float2 mu2  = ld2(mu,   o);
    const float l2m0 = lam2.x + 2.0f * mu2.x;
    const float l2m1 = lam2.y + 2.0f * mu2.y;
    const bool ybord = (y < 2 || y >= NG - 2);
    const float mk0 = (ybord || x0     < 2 || x0     >= NG - 2) ? 0.0f : 1.0f;
    const float mk1 = (ybord || x0 + 1 < 2 || x0 + 1 >= NG - 2) ? 0.0f : 1.0f;

    // source masks for this shot: bit s -> cell0, bit s+8 -> cell1
    unsigned smask = 0u;
#pragma unroll
    for (int s = 0; s < NSRC; s++) {
        int sy = sloc[(shot*NSRC + s)*2], sx = sloc[(shot*NSRC + s)*2 + 1];
        if (sy == y && sx == x0)     smask |= 1u << s;
        if (sy == y && sx == x0 + 1) smask |= 1u << (s + 8);
    }

    // receiver ownership for this shot
    int rcode[8];
    int rcnt = 0;
    bool rovf = false;
    for (int r = 0; r < NREC; r++) {
        int e = shot * NREC + r;
        int ry = rloc[e*2], rx = rloc[e*2 + 1];
        if (ry == y && (rx == x0 || rx == x0 + 1)) {
            if (rcnt < 8) rcode[rcnt++] = e * 2 + (rx - x0);
            else rovf = true;
        }
    }

    // ---- ring cells (threads 0..239): cross-shaped 2-wide ring ----
    const bool has_ring = (tid < NRING);
    int r_ey = 0, r_ex = 0, r_gy = 0, r_gx = 0;
    if (has_ring) {
        int k = tid;
        if (k < 80)       { r_ey = k / 40;              r_ex = 2 + (k % 40); }
        else if (k < 160) { r_ey = 22 + (k - 80) / 40;  r_ex = 2 + ((k - 80) % 40); }
        else if (k < 200) { r_ey = 2 + (k - 160) % 20;  r_ex = (k - 160) / 20; }
        else              { r_ey = 2 + (k - 200) % 20;  r_ex = 42 + (k - 200) / 20; }
        r_gy = (by0 + r_ey - 2 + NG) % NG;
        r_gx = (bx0 + r_ex - 2 + NG) % NG;
    }
    const int gro   = r_gy * NG;
    const int grym1 = ((r_gy + NG - 1) % NG) * NG;
    const int grym2 = ((r_gy + NG - 2) % NG) * NG;
    const int gryp1 = ((r_gy + 1) % NG) * NG;
    const int gryp2 = ((r_gy + 2) % NG) * NG;
    const int gxm1 = (r_gx + NG - 1) % NG, gxm2 = (r_gx + NG - 2) % NG;
    const int gxp1 = (r_gx + 1) % NG,      gxp2 = (r_gx + 2) % NG;
    const int ro = gro + r_gx;
    const float rbyv = pml_b(r_gy);
    const float rbxv = pml_b(r_gx);
    const float rbv  = buoy[ro];
    const float rmk  = (r_gy < 2 || r_gy >= NG-2 || r_gx < 2 || r_gx >= NG-2) ? 0.0f : 1.0f;
    unsigned rsmask = 0u;
    if (has_ring) {
#pragma unroll
        for (int s = 0; s < NSRC; s++)
            if (sloc[(shot*NSRC + s)*2] == r_gy && sloc[(shot*NSRC + s)*2 + 1] == r_gx)
                rsmask |= 1u << s;
    }

    // ---- register state (single shot, 2 cells) ----
    float vy[2]  = {0,0}, vx[2]  = {0,0};
    float syy[2] = {0,0}, sxy[2] = {0,0}, sxx[2] = {0,0};
    float m_vyy[2]  = {0,0}, m_vyx[2]  = {0,0};
    float m_vxy[2]  = {0,0}, m_vxx[2]  = {0,0};
    float m_syyy[2] = {0,0}, m_sxyy[2] = {0,0};
    float m_sxyx[2] = {0,0}, m_sxxx[2] = {0,0};
    float r_vy = 0, r_vx = 0;
    float r_msyyy = 0, r_msxyy = 0, r_msxyx = 0, r_msxxx = 0;

    // zero stress buffer 2 on own core: read as str(-1) by step 0
    {
        int i = base + o;
        st2(g_syy[2], i, 0.f, 0.f);
        st2(g_sxy[2], i, 0.f, 0.f);
        st2(g_sxx[2], i, 0.f, 0.f);
    }
    __syncthreads();
    if (tid == 0) { __threadfence(); red_add(&g_flag[blk * 32]); }   // flag = F+1

    const float C1 = 1.125f;
    const float C2 = -1.0f / 24.0f;

#pragma unroll 1
    for (int t = 0; t < NT; t++) {
        // wait for 8 same-shot neighbors to have completed step t-1
        if (tid < 8) {
            const unsigned tgt = F + 1u + (unsigned)t;
            const unsigned* fp = &g_flag[nbid * 32];
            while ((int)(ld_acq(fp) - tgt) < 0) { }
        }
        __syncthreads();

        const int p = (t + 2) % 3;     // read buffer: str(t-1)
        const int q = t % 3;           // write buffer: str(t)
        const float* __restrict__ Syy = g_syy[p];
        const float* __restrict__ Sxy = g_sxy[p];
        const float* __restrict__ Sxx = g_sxx[p];

        // ================= velocity: core =================
        {
            float d0, d1, m;

            float2 a_ym1 = ld2(Syy, base + rym1 + x0);
            float2 a_ym2 = ld2(Syy, base + rym2 + x0);
            float2 a_yp1 = ld2(Syy, base + ryp1 + x0);
            d0 = (C1*(syy[0] - a_ym1.x) + C2*(a_yp1.x - a_ym2.x)) * IDHF;
            d1 = (C1*(syy[1] - a_ym1.y) + C2*(a_yp1.y - a_ym2.y)) * IDHF;
            m = m_syyy[0]; m = byv*m + (byv-1.0f)*d0; m_syyy[0] = m;
            float ay0 = d0 + m;
            m = m_syyy[1]; m = byv*m + (byv-1.0f)*d1; m_syyy[1] = m;
            float ay1 = d1 + m;

            float2 u_xm = ld2(Sxy, base + row + xm2c);
            float2 u_xp = ld2(Sxy, base + row + xp2c);
            d0 = (C1*(sxy[1] - sxy[0]) + C2*(u_xp.x - u_xm.y)) * IDHF;
            d1 = (C1*(u_xp.x - sxy[1]) + C2*(u_xp.y - sxy[0])) * IDHF;
            m = m_sxyx[0]; m = bxv0*m + (bxv0-1.0f)*d0; m_sxyx[0] = m;
            ay0 += d0 + m;
            m = m_sxyx[1]; m = bxv1*m + (bxv1-1.0f)*d1; m_sxyx[1] = m;
            ay1 += d1 + m;

            vy[0] += DTF * bv2.x * ay0;
            vy[1] += DTF * bv2.y * ay1;

            float2 w_xm = ld2(Sxx, base + row + xm2c);
            float2 w_xp = ld2(Sxx, base + row + xp2c);
            d0 = (C1*(sxx[0] - w_xm.y) + C2*(sxx[1] - w_xm.x)) * IDHF;
            d1 = (C1*(sxx[1] - sxx[0]) + C2*(w_xp.x - w_xm.y)) * IDHF;
            m = m_sxxx[0]; m = bxv0*m + (bxv0-1.0f)*d0; m_sxxx[0] = m;
            float ax0 = d0 + m;
            m = m_sxxx[1]; m = bxv1*m + (bxv1-1.0f)*d1; m_sxxx[1] = m;
            float ax1 = d1 + m;

            float2 s_yp1v = ld2(Sxy, base + ryp1 + x0);
            float2 s_yp2v = ld2(Sxy, base + ryp2 + x0);
            float2 s_ym1v = ld2(Sxy, base + rym1 + x0);
            d0 = (C1*(s_yp1v.x - sxy[0]) + C2*(s_yp2v.x - s_ym1v.x)) * IDHF;
            d1 = (C1*(s_yp1v.y - sxy[1]) + C2*(s_yp2v.y - s_ym1v.y)) * IDHF;
            m = m_sxyy[0]; m = byv*m + (byv-1.0f)*d0; m_sxyy[0] = m;
            ax0 += d0 + m;
            m = m_sxyy[1]; m = byv*m + (byv-1.0f)*d1; m_sxyy[1] = m;
            ax1 += d1 + m;

            vx[0] += DTF * bv2.x * ax0;
            vx[1] += DTF * bv2.y * ax1;

            if (smask) {
#pragma unroll
                for (int s = 0; s < NSRC; s++) {
                    if (smask & (1u << s))
                        vy[0] += DTF * amps[(shot*NSRC + s)*NT + t] * bv2.x;
                    if (smask & (1u << (s + 8)))
                        vy[1] += DTF * amps[(shot*NSRC + s)*NT + t] * bv2.y;
                }
            }
            vy[0] *= mk0; vy[1] *= mk1;
            vx[0] *= mk0; vx[1] *= mk1;

            s_vy[2+rr][2+2*pp]   = vy[0];
            s_vy[2+rr][2+2*pp+1] = vy[1];
            s_vx[2+rr][2+2*pp]   = vx[0];
            s_vx[2+rr][2+2*pp+1] = vx[1];
        }

        // ================= velocity: ring =================
        if (has_ring) {
            float d, m;

            d = (C1*(Syy[base+ro] - Syy[base+grym1+r_gx])
               + C2*(Syy[base+gryp1+r_gx] - Syy[base+grym2+r_gx])) * IDHF;
            m = r_msyyy; m = rbyv*m + (rbyv-1.0f)*d; r_msyyy = m;
            float ay = d + m;

            d = (C1*(Sxy[base+gro+gxp1] - Sxy[base+ro])
               + C2*(Sxy[base+gro+gxp2] - Sxy[base+gro+gxm1])) * IDHF;
            m = r_msxyx; m = rbxv*m + (rbxv-1.0f)*d; r_msxyx = m;
            ay += d + m;

            r_vy += DTF * rbv * ay;

            d = (C1*(Sxx[base+ro] - Sxx[base+gro+gxm1])
               + C2*(Sxx[base+gro+gxp1] - Sxx[base+gro+gxm2])) * IDHF;
            m = r_msxxx; m = rbxv*m + (rbxv-1.0f)*d; r_msxxx = m;
            float ax = d + m;

            d = (C1*(Sxy[base+gryp1+r_gx] - Sxy[base+ro])
               + C2*(Sxy[base+gryp2+r_gx] - Sxy[base+grym1+r_gx])) * IDHF;
            m = r_msxyy; m = rbyv*m + (rbyv-1.0f)*d; r_msxyy = m;
            ax += d + m;

            r_vx += DTF * rbv * ax;

            if (rsmask) {
#pragma unroll
                for (int s = 0; s < NSRC; s++)
                    if (rsmask & (1u << s))
                        r_vy += DTF * amps[(shot*NSRC + s)*NT + t] * rbv;
            }
            r_vy *= rmk;
            r_vx *= rmk;
            s_vy[r_ey][r_ex] = r_vy;
            s_vx[r_ey][r_ex] = r_vx;
        }

        // receivers (owner records from registers)
        if (rovf) {
            for (int r = 0; r < NREC; r++) {
                int e = shot * NREC + r;
                int ry = rloc[e*2], rx = rloc[e*2 + 1];
                if (ry == y && (rx == x0 || rx == x0 + 1))
                    g_recs[t*(NSHOT*NREC) + e] = vy[rx - x0];
            }
        } else {
            for (int i = 0; i < rcnt; i++) {
                int e = rcode[i] >> 1, c = rcode[i] & 1;
                g_recs[t*(NSHOT*NREC) + e] = vy[c];
            }
        }

        __syncthreads();

        // ================= stress: core (SMEM taps) =================
        {
            const int sy = 2 + rr, sx = 2 + 2*pp;
            float d0, d1, m;

            d0 = (C1*(s_vy[sy+1][sx]   - vy[0])
                + C2*(s_vy[sy+2][sx]   - s_vy[sy-1][sx])) * IDHF;
            d1 = (C1*(s_vy[sy+1][sx+1] - vy[1])
                + C2*(s_vy[sy+2][sx+1] - s_vy[sy-1][sx+1])) * IDHF;
            m = m_vyy[0]; m = byv*m + (byv-1.0f)*d0; m_vyy[0] = m;
            float e10 = d0 + m;
            m = m_vyy[1]; m = byv*m + (byv-1.0f)*d1; m_vyy[1] = m;
            float e11 = d1 + m;

            float vxm1 = s_vx[sy][sx-1], vxm2 = s_vx[sy][sx-2];
            float vxp2 = s_vx[sy][sx+2];
            d0 = (C1*(vx[0] - vxm1) + C2*(vx[1] - vxm2)) * IDHF;
            d1 = (C1*(vx[1] - vx[0]) + C2*(vxp2 - vxm1)) * IDHF;
            m = m_vxx[0]; m = bxv0*m + (bxv0-1.0f)*d0; m_vxx[0] = m;
            float e20 = d0 + m;
            m = m_vxx[1]; m = bxv1*m + (bxv1-1.0f)*d1; m_vxx[1] = m;
            float e21 = d1 + m;

            syy[0] = (syy[0] + DTF*(l2m0*e10 + lam2.x*e20)) * mk0;
            syy[1] = (syy[1] + DTF*(l2m1*e11 + lam2.y*e21)) * mk1;
            sxx[0] = (sxx[0] + DTF*(l2m0*e20 + lam2.x*e10)) * mk0;
            sxx[1] = (sxx[1] + DTF*(l2m1*e21 + lam2.y*e11)) * mk1;

            float vym1 = s_vy[sy][sx-1];
            float vyp2 = s_vy[sy][sx+2], vyp3 = s_vy[sy][sx+3];
            d0 = (C1*(vy[1] - vy[0]) + C2*(vyp2 - vym1)) * IDHF;
            d1 = (C1*(vyp2 - vy[1]) + C2*(vyp3 - vy[0])) * IDHF;
            m = m_vyx[0]; m = bxv0*m + (bxv0-1.0f)*d0; m_vyx[0] = m;
            float g0 = d0 + m;
            m = m_vyx[1]; m = bxv1*m + (bxv1-1.0f)*d1; m_vyx[1] = m;
            float g1 = d1 + m;

            d0 = (C1*(vx[0] - s_vx[sy-1][sx])
                + C2*(s_vx[sy+1][sx] - s_vx[sy-2][sx])) * IDHF;
            d1 = (C1*(vx[1] - s_vx[sy-1][sx+1])
                + C2*(s_vx[sy+1][sx+1] - s_vx[sy-2][sx+1])) * IDHF;
            m = m_vxy[0]; m = byv*m + (byv-1.0f)*d0; m_vxy[0] = m;
            g0 += d0 + m;
            m = m_vxy[1]; m = byv*m + (byv-1.0f)*d1; m_vxy[1] = m;
            g1 += d1 + m;

            sxy[0] = (sxy[0] + DTF*mu2.x*g0) * mk0;
            sxy[1] = (sxy[1] + DTF*mu2.y*g1) * mk1;

            st2(g_syy[q], base + o, syy[0], syy[1]);
            st2(g_sxy[q], base + o, sxy[0], sxy[1]);
            st2(g_sxx[q], base + o, sxx[0], sxx[1]);
        }

        // publish step t completion
        __syncthreads();
        if (tid == 0) { __threadfence(); red_add(&g_flag[blk * 32]); }
    }

    // ---------------- finalize (needs all blocks' g_recs) ----------------
    gbar(ph + 1);
    const int gtid = blk * TPB + tid;
    const int total = NSHOT * NREC * (NT - 1);
    if (gtid < total) {
        int t = gtid % (NT - 1);
        int e = gtid / (NT - 1);
        out[e * (NT - 1) + t] = 0.5f * (g_recs[(t + 1)*(NSHOT*NREC) + e]
                                      + g_recs[t      *(NSHOT*NREC) + e]);
    }
}

extern "C" void kernel_launch(void* const* d_in, const int* in_sizes, int n_in,
                              void* d_out, int out_size)
{
    const float* lamb = (const float*)d_in[0];
    const float* mu   = (const float*)d_in[1];
    const float* buoy = (const float*)d_in[2];
    const float* amps = (const float*)d_in[3];
    const int*   sloc = (const int*)d_in[4];
    const int*   rloc = (const int*)d_in[5];
    float* out = (float*)d_out;

    sim_kernel<<<NBLK, TPB>>>(lamb, mu, buoy, amps, sloc, rloc, out);
}